// round 4
// baseline (speedup 1.0000x reference)
#include <cuda_runtime.h>
#include <cuda_fp16.h>
#include <cstdint>

// ---------------------------------------------------------------------------
// Problem constants
// ---------------------------------------------------------------------------
#define B_ROWS 4096
#define D_DIM  512
#define C_DIM  20000

#define BM 256
#define BN 128
#define BK 64                   // 64 fp16 = 128B rows (SW128 atom)
#define NK (D_DIM / BK)         // 8 k-iterations
#define STAGES 4
#define THREADS 256

#define STAGE_BYTES ((BM + BN) * BK * 2)   // 49152
#define SMEM_BYTES  (STAGES * STAGE_BYTES + 1024)

static __device__ __half g_f16[(size_t)B_ROWS * D_DIM];   // normalized feat, fp16
static __device__ __half g_w16[(size_t)C_DIM * D_DIM];    // normalized weights, fp16

// ArcFace constants
#define AF_SCALE  30.0f
#define AF_COSM   0.87758256189037271612f   // cos(0.5)
#define AF_SINM   0.47942553860420300027f   // sin(0.5)
#define AF_THRESH (-0.87758256189037271612f)
#define AF_EXTV   (-0.23971276930210150013f) // -0.5*sin(0.5)

// ---------------------------------------------------------------------------
// PTX helpers (all non-'a' features: sm_80/sm_75 baseline)
// ---------------------------------------------------------------------------
__device__ __forceinline__ uint32_t smem_u32(const void* p) {
    uint32_t a;
    asm("{ .reg .u64 t; cvta.to.shared.u64 t, %1; cvt.u32.u64 %0, t; }"
        : "=r"(a) : "l"(p));
    return a;
}

__device__ __forceinline__ uint32_t sw128(uint32_t off) {
    return off ^ ((off >> 3) & 0x70);
}

__device__ __forceinline__ void cp_async16(uint32_t dst, const void* src,
                                           uint32_t ssize) {
    asm volatile("cp.async.cg.shared.global [%0], [%1], 16, %2;"
                 :: "r"(dst), "l"(src), "r"(ssize));
}
#define CP_COMMIT() asm volatile("cp.async.commit_group;" ::: "memory")
#define CP_WAIT(n)  asm volatile("cp.async.wait_group %0;" :: "n"(n) : "memory")

#define LDSM_X4(r, addr) \
    asm volatile("ldmatrix.sync.aligned.m8n8.x4.shared.b16 {%0,%1,%2,%3}, [%4];" \
        : "=r"((r)[0]), "=r"((r)[1]), "=r"((r)[2]), "=r"((r)[3]) : "r"(addr))

__device__ __forceinline__ void mma_16816(float* d, const uint32_t* a,
                                          uint32_t b0, uint32_t b1) {
    asm volatile(
        "mma.sync.aligned.m16n8k16.row.col.f32.f16.f16.f32 "
        "{%0,%1,%2,%3}, {%4,%5,%6,%7}, {%8,%9}, {%0,%1,%2,%3};"
        : "+f"(d[0]), "+f"(d[1]), "+f"(d[2]), "+f"(d[3])
        : "r"(a[0]), "r"(a[1]), "r"(a[2]), "r"(a[3]), "r"(b0), "r"(b1));
}

// ---------------------------------------------------------------------------
// Kernel 1/2: row L2-normalize fp32 -> fp16 (one block of 128 threads per row)
// ---------------------------------------------------------------------------
__global__ void norm_rows_kernel(const float* __restrict__ src,
                                 __half* __restrict__ dst) {
    const int row = blockIdx.x;
    const int tid = threadIdx.x;
    const float4 v = reinterpret_cast<const float4*>(src + (size_t)row * D_DIM)[tid];
    float ss = v.x * v.x + v.y * v.y + v.z * v.z + v.w * v.w;
    #pragma unroll
    for (int o = 16; o; o >>= 1) ss += __shfl_xor_sync(0xFFFFFFFFu, ss, o);
    __shared__ float ws[4];
    if ((tid & 31) == 0) ws[tid >> 5] = ss;
    __syncthreads();
    const float inv = rsqrtf(ws[0] + ws[1] + ws[2] + ws[3]);
    __half2 h0 = __floats2half2_rn(v.x * inv, v.y * inv);
    __half2 h1 = __floats2half2_rn(v.z * inv, v.w * inv);
    uint2 pk;
    pk.x = *reinterpret_cast<uint32_t*>(&h0);
    pk.y = *reinterpret_cast<uint32_t*>(&h1);
    reinterpret_cast<uint2*>(dst + (size_t)row * D_DIM)[tid] = pk;
}

// ---------------------------------------------------------------------------
// Tile loader: A[256x64] + B[128x64] fp16 into SW128-swizzled smem via cp.async
// ---------------------------------------------------------------------------
__device__ __forceinline__ void load_tiles(uint32_t sA, uint32_t sB,
                                           int m0, int n0, int kk, int tid) {
    // A: 256 rows x 8 16B-chunks = 2048 chunks -> 8 per thread
    #pragma unroll
    for (int i = 0; i < 8; i++) {
        int s = tid + i * THREADS;
        int row = s >> 3, c16 = s & 7;
        const __half* src = g_f16 + (size_t)(m0 + row) * D_DIM + kk + c16 * 8;
        cp_async16(sA + sw128((uint32_t)(row * 128 + c16 * 16)), src, 16u);
    }
    // B: 128 rows x 8 chunks = 1024 -> 4 per thread
    #pragma unroll
    for (int i = 0; i < 4; i++) {
        int s = tid + i * THREADS;
        int row = s >> 3, c16 = s & 7;
        int n = n0 + row;
        int nc = (n < C_DIM) ? n : 0;
        const __half* src = g_w16 + (size_t)nc * D_DIM + kk + c16 * 8;
        cp_async16(sB + sw128((uint32_t)(row * 128 + c16 * 16)), src,
                   (n < C_DIM) ? 16u : 0u);
    }
}

// ---------------------------------------------------------------------------
// ArcFace margin for the label column
// ---------------------------------------------------------------------------
__device__ __forceinline__ float af_margin(float c) {
    if (c > AF_THRESH) {
        float s = sqrtf(fmaxf(0.0f, 1.0f - c * c));
        return AF_SCALE * (c * AF_COSM - s * AF_SINM);
    }
    return AF_SCALE * (c + AF_EXTV);
}

// ---------------------------------------------------------------------------
// Kernel 3: mma.sync GEMM, 256x128 block tile, 64x64 warp tiles (4m x 2n),
// 4-stage cp.async pipeline. Fused ArcFace epilogue (cos + marginal logits).
// ---------------------------------------------------------------------------
__global__ void __launch_bounds__(THREADS)
arcface_gemm_kernel(const int* __restrict__ label,
                    float* __restrict__ cos_out, float* __restrict__ marg_out) {
    extern __shared__ char dsmem[];
    uint32_t sbase = (smem_u32(dsmem) + 1023u) & ~1023u;

    const int tid  = threadIdx.x;
    const int lane = tid & 31;
    const int wid  = tid >> 5;
    const int warp_m = wid & 3;     // 0..3  (64-row slab)
    const int warp_n = wid >> 2;    // 0..1  (64-col slab)
    const int n0 = blockIdx.x * BN;
    const int m0 = blockIdx.y * BM;

    float acc[4][8][4];
    #pragma unroll
    for (int mt = 0; mt < 4; mt++)
        #pragma unroll
        for (int nt = 0; nt < 8; nt++)
            #pragma unroll
            for (int e = 0; e < 4; e++) acc[mt][nt][e] = 0.0f;

    // prologue: fill stages 0..2
    #pragma unroll
    for (int p = 0; p < STAGES - 1; p++) {
        uint32_t s = sbase + p * STAGE_BYTES;
        load_tiles(s, s + BM * 128, m0, n0, p * BK, tid);
        CP_COMMIT();
    }

    // lane-constant pieces of the swizzled ldmatrix addresses
    const uint32_t a_lane_off =
        (uint32_t)((warp_m * 64 + (lane & 15)) * 128 + (lane >> 4) * 16);
    const uint32_t b_lane_off =
        (uint32_t)((warp_n * 64 + (lane & 15)) * 128 + (lane >> 4) * 16);

    for (int k = 0; k < NK; k++) {
        CP_WAIT(STAGES - 2);
        __syncthreads();

        if (k + STAGES - 1 < NK) {
            int st = (k + STAGES - 1) % STAGES;
            uint32_t s = sbase + st * STAGE_BYTES;
            load_tiles(s, s + BM * 128, m0, n0, (k + STAGES - 1) * BK, tid);
        }
        CP_COMMIT();

        const uint32_t sA = sbase + (k % STAGES) * STAGE_BYTES;
        const uint32_t sB = sA + BM * 128;

        #pragma unroll
        for (int ks = 0; ks < 4; ks++) {
            uint32_t a_frag[4][4];
            #pragma unroll
            for (int mt = 0; mt < 4; mt++)
                LDSM_X4(a_frag[mt],
                        sA + sw128(a_lane_off + (uint32_t)(mt * 16 * 128 + ks * 32)));
            // B: ldmatrix.x4 covers two 8-col n-tiles at once
            // m0: n0-7/k0-7, m1: n8-15/k0-7, m2: n0-7/k8-15, m3: n8-15/k8-15
            uint32_t b_frag[4][4];
            #pragma unroll
            for (int g = 0; g < 4; g++)
                LDSM_X4(b_frag[g],
                        sB + sw128(b_lane_off + (uint32_t)(g * 16 * 128 + ks * 32)));
            #pragma unroll
            for (int mt = 0; mt < 4; mt++)
                #pragma unroll
                for (int nt = 0; nt < 8; nt++) {
                    int g = nt >> 1, w = nt & 1;
                    mma_16816(acc[mt][nt], a_frag[mt],
                              b_frag[g][w], b_frag[g][w + 2]);
                }
        }
    }

    // --- fused epilogue: cos + ArcFace marginal logits, float2 stores ---
    const int mrow  = m0 + warp_m * 64 + (lane >> 2);
    const int ncol0 = n0 + warp_n * 64 + (lane & 3) * 2;
    #pragma unroll
    for (int mt = 0; mt < 4; mt++) {
        const int m1 = mrow + mt * 16;
        const int m2 = m1 + 8;
        const int lab1 = label[m1];
        const int lab2 = label[m2];
        #pragma unroll
        for (int nt = 0; nt < 8; nt++) {
            int n = ncol0 + nt * 8;
            if (n >= C_DIM) continue;
            float c0 = acc[mt][nt][0], c1 = acc[mt][nt][1];
            float c2 = acc[mt][nt][2], c3 = acc[mt][nt][3];
            size_t o1 = (size_t)m1 * C_DIM + n;
            size_t o2 = (size_t)m2 * C_DIM + n;
            *reinterpret_cast<float2*>(cos_out + o1) = make_float2(c0, c1);
            *reinterpret_cast<float2*>(cos_out + o2) = make_float2(c2, c3);
            float g0 = (n     == lab1) ? af_margin(c0) : AF_SCALE * c0;
            float g1 = (n + 1 == lab1) ? af_margin(c1) : AF_SCALE * c1;
            float g2 = (n     == lab2) ? af_margin(c2) : AF_SCALE * c2;
            float g3 = (n + 1 == lab2) ? af_margin(c3) : AF_SCALE * c3;
            *reinterpret_cast<float2*>(marg_out + o1) = make_float2(g0, g1);
            *reinterpret_cast<float2*>(marg_out + o2) = make_float2(g2, g3);
        }
    }
}

// ---------------------------------------------------------------------------
// Launch
// ---------------------------------------------------------------------------
extern "C" void kernel_launch(void* const* d_in, const int* in_sizes, int n_in,
                              void* d_out, int out_size) {
    const float* feat  = (const float*)d_in[0];
    const int*   label = (const int*)d_in[1];
    const float* wts   = (const float*)d_in[2];
    float* cos_out  = (float*)d_out;
    float* marg_out = cos_out + (size_t)B_ROWS * C_DIM;

    __half* f16p = nullptr;
    __half* w16p = nullptr;
    cudaGetSymbolAddress((void**)&f16p, g_f16);
    cudaGetSymbolAddress((void**)&w16p, g_w16);

    norm_rows_kernel<<<B_ROWS, 128>>>(feat, f16p);
    norm_rows_kernel<<<C_DIM, 128>>>(wts, w16p);

    cudaFuncSetAttribute(arcface_gemm_kernel,
                         cudaFuncAttributeMaxDynamicSharedMemorySize,
                         SMEM_BYTES);

    dim3 grid((C_DIM + BN - 1) / BN, B_ROWS / BM);   // (157, 16)
    arcface_gemm_kernel<<<grid, THREADS, SMEM_BYTES>>>(label, cos_out, marg_out);
}

// round 5
// speedup vs baseline: 1.2024x; 1.2024x over previous
#include <cuda_runtime.h>
#include <cuda_fp16.h>
#include <cstdint>

// ---------------------------------------------------------------------------
// Problem constants
// ---------------------------------------------------------------------------
#define B_ROWS 4096
#define D_DIM  512
#define C_DIM  20000

#define BM 128
#define BN 128
#define BK 64                   // 64 fp16 = 128B rows (SW128 atom)
#define NK (D_DIM / BK)         // 8 k-iterations
#define STAGES 3
#define THREADS 256

#define STAGE_BYTES ((BM + BN) * BK * 2)   // 32768
#define SMEM_BYTES  (STAGES * STAGE_BYTES + 1024)

static __device__ __half g_f16[(size_t)B_ROWS * D_DIM];   // normalized feat, fp16
static __device__ __half g_w16[(size_t)C_DIM * D_DIM];    // normalized weights, fp16

// ArcFace constants
#define AF_SCALE  30.0f
#define AF_COSM   0.87758256189037271612f   // cos(0.5)
#define AF_SINM   0.47942553860420300027f   // sin(0.5)
#define AF_THRESH (-0.87758256189037271612f)
#define AF_EXTV   (-0.23971276930210150013f) // -0.5*sin(0.5)

// ---------------------------------------------------------------------------
// PTX helpers
// ---------------------------------------------------------------------------
__device__ __forceinline__ uint32_t smem_u32(const void* p) {
    uint32_t a;
    asm("{ .reg .u64 t; cvta.to.shared.u64 t, %1; cvt.u32.u64 %0, t; }"
        : "=r"(a) : "l"(p));
    return a;
}

__device__ __forceinline__ uint32_t sw128(uint32_t off) {
    return off ^ ((off >> 3) & 0x70);
}

__device__ __forceinline__ void cp_async16(uint32_t dst, const void* src,
                                           uint32_t ssize) {
    asm volatile("cp.async.cg.shared.global [%0], [%1], 16, %2;"
                 :: "r"(dst), "l"(src), "r"(ssize));
}
#define CP_COMMIT() asm volatile("cp.async.commit_group;" ::: "memory")
#define CP_WAIT(n)  asm volatile("cp.async.wait_group %0;" :: "n"(n) : "memory")

#define LDSM_X4(r, addr) \
    asm volatile("ldmatrix.sync.aligned.m8n8.x4.shared.b16 {%0,%1,%2,%3}, [%4];" \
        : "=r"((r)[0]), "=r"((r)[1]), "=r"((r)[2]), "=r"((r)[3]) : "r"(addr))

__device__ __forceinline__ void mma_16816(float* d, const uint32_t* a,
                                          uint32_t b0, uint32_t b1) {
    asm volatile(
        "mma.sync.aligned.m16n8k16.row.col.f32.f16.f16.f32 "
        "{%0,%1,%2,%3}, {%4,%5,%6,%7}, {%8,%9}, {%0,%1,%2,%3};"
        : "+f"(d[0]), "+f"(d[1]), "+f"(d[2]), "+f"(d[3])
        : "r"(a[0]), "r"(a[1]), "r"(a[2]), "r"(a[3]), "r"(b0), "r"(b1));
}

// streaming (evict-first) float2 store — keeps inputs resident in L2
__device__ __forceinline__ void st_cs_f2(float* p, float x, float y) {
    asm volatile("st.global.cs.v2.f32 [%0], {%1, %2};"
                 :: "l"(p), "f"(x), "f"(y) : "memory");
}

// ---------------------------------------------------------------------------
// Kernel 1: row L2-normalize fp32 -> fp16, both tensors in one launch
// ---------------------------------------------------------------------------
__global__ void norm_rows_kernel(const float* __restrict__ feat,
                                 const float* __restrict__ wts) {
    int row = blockIdx.x;
    const float* src;
    __half* dst;
    if (row < B_ROWS) {
        src = feat + (size_t)row * D_DIM;
        dst = g_f16 + (size_t)row * D_DIM;
    } else {
        row -= B_ROWS;
        src = wts + (size_t)row * D_DIM;
        dst = g_w16 + (size_t)row * D_DIM;
    }
    const int tid = threadIdx.x;
    const float4 v = reinterpret_cast<const float4*>(src)[tid];
    float ss = v.x * v.x + v.y * v.y + v.z * v.z + v.w * v.w;
    #pragma unroll
    for (int o = 16; o; o >>= 1) ss += __shfl_xor_sync(0xFFFFFFFFu, ss, o);
    __shared__ float ws[4];
    if ((tid & 31) == 0) ws[tid >> 5] = ss;
    __syncthreads();
    const float inv = rsqrtf(ws[0] + ws[1] + ws[2] + ws[3]);
    __half2 h0 = __floats2half2_rn(v.x * inv, v.y * inv);
    __half2 h1 = __floats2half2_rn(v.z * inv, v.w * inv);
    uint2 pk;
    pk.x = *reinterpret_cast<uint32_t*>(&h0);
    pk.y = *reinterpret_cast<uint32_t*>(&h1);
    reinterpret_cast<uint2*>(dst)[tid] = pk;
}

// ---------------------------------------------------------------------------
// Tile loader: A[128x64] + B[128x64] fp16 into SW128-swizzled smem via cp.async
// ---------------------------------------------------------------------------
__device__ __forceinline__ void load_tiles(uint32_t sA, uint32_t sB,
                                           int m0, int n0, int kk, int tid) {
    #pragma unroll
    for (int i = 0; i < 4; i++) {
        int s = tid + i * THREADS;            // 0..1023
        int row = s >> 3, c16 = s & 7;
        const __half* src = g_f16 + (size_t)(m0 + row) * D_DIM + kk + c16 * 8;
        cp_async16(sA + sw128((uint32_t)(row * 128 + c16 * 16)), src, 16u);
    }
    #pragma unroll
    for (int i = 0; i < 4; i++) {
        int s = tid + i * THREADS;
        int row = s >> 3, c16 = s & 7;
        int n = n0 + row;
        int nc = (n < C_DIM) ? n : 0;
        const __half* src = g_w16 + (size_t)nc * D_DIM + kk + c16 * 8;
        cp_async16(sB + sw128((uint32_t)(row * 128 + c16 * 16)), src,
                   (n < C_DIM) ? 16u : 0u);
    }
}

// ---------------------------------------------------------------------------
// ArcFace margin for the label column
// ---------------------------------------------------------------------------
__device__ __forceinline__ float af_margin(float c) {
    if (c > AF_THRESH) {
        float s = sqrtf(fmaxf(0.0f, 1.0f - c * c));
        return AF_SCALE * (c * AF_COSM - s * AF_SINM);
    }
    return AF_SCALE * (c + AF_EXTV);
}

// ---------------------------------------------------------------------------
// Kernel 2: mma.sync GEMM, 128x128 block tile, 64x32 warp tiles (2m x 4n),
// 3-stage cp.async pipeline. Fused ArcFace epilogue with streaming stores.
// ---------------------------------------------------------------------------
__global__ void __launch_bounds__(THREADS)
arcface_gemm_kernel(const int* __restrict__ label,
                    float* __restrict__ cos_out, float* __restrict__ marg_out) {
    extern __shared__ char dsmem[];
    uint32_t sbase = (smem_u32(dsmem) + 1023u) & ~1023u;

    const int tid  = threadIdx.x;
    const int lane = tid & 31;
    const int wid  = tid >> 5;
    const int warp_m = wid & 1;     // 0..1  (64-row slab)
    const int warp_n = wid >> 1;    // 0..3  (32-col slab)
    const int n0 = blockIdx.x * BN;
    const int m0 = blockIdx.y * BM;

    float acc[4][4][4];
    #pragma unroll
    for (int mt = 0; mt < 4; mt++)
        #pragma unroll
        for (int nt = 0; nt < 4; nt++)
            #pragma unroll
            for (int e = 0; e < 4; e++) acc[mt][nt][e] = 0.0f;

    // prologue: fill stages 0,1
    load_tiles(sbase + 0 * STAGE_BYTES, sbase + 0 * STAGE_BYTES + BM * 128,
               m0, n0, 0, tid);
    CP_COMMIT();
    load_tiles(sbase + 1 * STAGE_BYTES, sbase + 1 * STAGE_BYTES + BM * 128,
               m0, n0, BK, tid);
    CP_COMMIT();

    // lane-constant pieces of the swizzled ldmatrix addresses
    const uint32_t a_lane_off =
        (uint32_t)((warp_m * 64 + (lane & 15)) * 128 + (lane >> 4) * 16);
    const uint32_t b_lane_off =
        (uint32_t)((warp_n * 32 + (lane & 15)) * 128 + (lane >> 4) * 16);

    for (int k = 0; k < NK; k++) {
        CP_WAIT(1);
        __syncthreads();

        if (k + STAGES - 1 < NK) {
            int st = (k + STAGES - 1) % STAGES;
            load_tiles(sbase + st * STAGE_BYTES,
                       sbase + st * STAGE_BYTES + BM * 128,
                       m0, n0, (k + STAGES - 1) * BK, tid);
        }
        CP_COMMIT();

        const uint32_t sA = sbase + (k % STAGES) * STAGE_BYTES;
        const uint32_t sB = sA + BM * 128;

        #pragma unroll
        for (int ks = 0; ks < 4; ks++) {
            uint32_t a_frag[4][4];
            #pragma unroll
            for (int mt = 0; mt < 4; mt++)
                LDSM_X4(a_frag[mt],
                        sA + sw128(a_lane_off + (uint32_t)(mt * 16 * 128 + ks * 32)));
            // B: two ldmatrix.x4, each covering 16 n-rows (two 8-col n-tiles)
            uint32_t b_frag[2][4];
            #pragma unroll
            for (int g = 0; g < 2; g++)
                LDSM_X4(b_frag[g],
                        sB + sw128(b_lane_off + (uint32_t)(g * 16 * 128 + ks * 32)));
            #pragma unroll
            for (int mt = 0; mt < 4; mt++)
                #pragma unroll
                for (int nt = 0; nt < 4; nt++) {
                    int g = nt >> 1, w = nt & 1;
                    mma_16816(acc[mt][nt], a_frag[mt],
                              b_frag[g][w], b_frag[g][w + 2]);
                }
        }
    }

    // --- fused epilogue: cos + ArcFace marginal logits, streaming stores ---
    const int mrow  = m0 + warp_m * 64 + (lane >> 2);
    const int ncol0 = n0 + warp_n * 32 + (lane & 3) * 2;
    #pragma unroll
    for (int mt = 0; mt < 4; mt++) {
        const int m1 = mrow + mt * 16;
        const int m2 = m1 + 8;
        const int lab1 = label[m1];
        const int lab2 = label[m2];
        #pragma unroll
        for (int nt = 0; nt < 4; nt++) {
            int n = ncol0 + nt * 8;
            if (n >= C_DIM) continue;
            float c0 = acc[mt][nt][0], c1 = acc[mt][nt][1];
            float c2 = acc[mt][nt][2], c3 = acc[mt][nt][3];
            size_t o1 = (size_t)m1 * C_DIM + n;
            size_t o2 = (size_t)m2 * C_DIM + n;
            st_cs_f2(cos_out + o1, c0, c1);
            st_cs_f2(cos_out + o2, c2, c3);
            float g0 = (n     == lab1) ? af_margin(c0) : AF_SCALE * c0;
            float g1 = (n + 1 == lab1) ? af_margin(c1) : AF_SCALE * c1;
            float g2 = (n     == lab2) ? af_margin(c2) : AF_SCALE * c2;
            float g3 = (n + 1 == lab2) ? af_margin(c3) : AF_SCALE * c3;
            st_cs_f2(marg_out + o1, g0, g1);
            st_cs_f2(marg_out + o2, g2, g3);
        }
    }
}

// ---------------------------------------------------------------------------
// Launch
// ---------------------------------------------------------------------------
extern "C" void kernel_launch(void* const* d_in, const int* in_sizes, int n_in,
                              void* d_out, int out_size) {
    const float* feat  = (const float*)d_in[0];
    const int*   label = (const int*)d_in[1];
    const float* wts   = (const float*)d_in[2];
    float* cos_out  = (float*)d_out;
    float* marg_out = cos_out + (size_t)B_ROWS * C_DIM;

    norm_rows_kernel<<<B_ROWS + C_DIM, 128>>>(feat, wts);

    cudaFuncSetAttribute(arcface_gemm_kernel,
                         cudaFuncAttributeMaxDynamicSharedMemorySize,
                         SMEM_BYTES);

    dim3 grid((C_DIM + BN - 1) / BN, B_ROWS / BM);   // (157, 32)
    arcface_gemm_kernel<<<grid, THREADS, SMEM_BYTES>>>(label, cos_out, marg_out);
}

// round 6
// speedup vs baseline: 1.2499x; 1.0396x over previous
#include <cuda_runtime.h>
#include <cuda_fp16.h>
#include <cstdint>

// ---------------------------------------------------------------------------
// Problem constants
// ---------------------------------------------------------------------------
#define B_ROWS 4096
#define D_DIM  512
#define C_DIM  20000

#define BM 128
#define BN 128
#define BK 64                   // 64 fp16 = 128B rows (SW128 atom)
#define NK (D_DIM / BK)         // 8 k-iterations
#define STAGES 3
#define THREADS 256

#define STAGE_BYTES ((BM + BN) * BK * 2)   // 32768
#define SMEM_BYTES  (STAGES * STAGE_BYTES + 1024)

static __device__ __half g_f16[(size_t)B_ROWS * D_DIM];   // normalized feat, fp16
static __device__ __half g_w16[(size_t)C_DIM * D_DIM];    // normalized weights, fp16

// ArcFace constants
#define AF_SCALE  30.0f
#define AF_COSM   0.87758256189037271612f   // cos(0.5)
#define AF_SINM   0.47942553860420300027f   // sin(0.5)
#define AF_THRESH (-0.87758256189037271612f)
#define AF_EXTV   (-0.23971276930210150013f) // -0.5*sin(0.5)

// ---------------------------------------------------------------------------
// PTX helpers
// ---------------------------------------------------------------------------
__device__ __forceinline__ uint32_t smem_u32(const void* p) {
    uint32_t a;
    asm("{ .reg .u64 t; cvta.to.shared.u64 t, %1; cvt.u32.u64 %0, t; }"
        : "=r"(a) : "l"(p));
    return a;
}

__device__ __forceinline__ void cp_async16(uint32_t dst, const void* src,
                                           uint32_t ssize) {
    asm volatile("cp.async.cg.shared.global [%0], [%1], 16, %2;"
                 :: "r"(dst), "l"(src), "r"(ssize));
}
#define CP_COMMIT() asm volatile("cp.async.commit_group;" ::: "memory")
#define CP_WAIT(n)  asm volatile("cp.async.wait_group %0;" :: "n"(n) : "memory")

#define LDSM_X4(r, addr) \
    asm volatile("ldmatrix.sync.aligned.m8n8.x4.shared.b16 {%0,%1,%2,%3}, [%4];" \
        : "=r"((r)[0]), "=r"((r)[1]), "=r"((r)[2]), "=r"((r)[3]) : "r"(addr))

__device__ __forceinline__ void mma_16816(float* d, const uint32_t* a,
                                          uint32_t b0, uint32_t b1) {
    asm volatile(
        "mma.sync.aligned.m16n8k16.row.col.f32.f16.f16.f32 "
        "{%0,%1,%2,%3}, {%4,%5,%6,%7}, {%8,%9}, {%0,%1,%2,%3};"
        : "+f"(d[0]), "+f"(d[1]), "+f"(d[2]), "+f"(d[3])
        : "r"(a[0]), "r"(a[1]), "r"(a[2]), "r"(a[3]), "r"(b0), "r"(b1));
}

// streaming (evict-first) float2 store — keeps inputs resident in L2
__device__ __forceinline__ void st_cs_f2(float* p, float x, float y) {
    asm volatile("st.global.cs.v2.f32 [%0], {%1, %2};"
                 :: "l"(p), "f"(x), "f"(y) : "memory");
}

// ---------------------------------------------------------------------------
// Kernel 1: row L2-normalize fp32 -> fp16, both tensors in one launch
// ---------------------------------------------------------------------------
__global__ void norm_rows_kernel(const float* __restrict__ feat,
                                 const float* __restrict__ wts) {
    int row = blockIdx.x;
    const float* src;
    __half* dst;
    if (row < B_ROWS) {
        src = feat + (size_t)row * D_DIM;
        dst = g_f16 + (size_t)row * D_DIM;
    } else {
        row -= B_ROWS;
        src = wts + (size_t)row * D_DIM;
        dst = g_w16 + (size_t)row * D_DIM;
    }
    const int tid = threadIdx.x;
    const float4 v = reinterpret_cast<const float4*>(src)[tid];
    float ss = v.x * v.x + v.y * v.y + v.z * v.z + v.w * v.w;
    #pragma unroll
    for (int o = 16; o; o >>= 1) ss += __shfl_xor_sync(0xFFFFFFFFu, ss, o);
    __shared__ float ws[4];
    if ((tid & 31) == 0) ws[tid >> 5] = ss;
    __syncthreads();
    const float inv = rsqrtf(ws[0] + ws[1] + ws[2] + ws[3]);
    __half2 h0 = __floats2half2_rn(v.x * inv, v.y * inv);
    __half2 h1 = __floats2half2_rn(v.z * inv, v.w * inv);
    uint2 pk;
    pk.x = *reinterpret_cast<uint32_t*>(&h0);
    pk.y = *reinterpret_cast<uint32_t*>(&h1);
    reinterpret_cast<uint2*>(dst)[tid] = pk;
}

// ---------------------------------------------------------------------------
// ArcFace margin for the label column
// ---------------------------------------------------------------------------
__device__ __forceinline__ float af_margin(float c) {
    if (c > AF_THRESH) {
        float s = sqrtf(fmaxf(0.0f, 1.0f - c * c));
        return AF_SCALE * (c * AF_COSM - s * AF_SINM);
    }
    return AF_SCALE * (c + AF_EXTV);
}

// ---------------------------------------------------------------------------
// Kernel 2: mma.sync GEMM, 128x128 block tile, 64x32 warp tiles (2m x 4n),
// 3-stage cp.async pipeline. All swizzle math hoisted out of the mainloop:
// SW128 XOR depends only on (row&7) == per-thread constant, and mt/ks/i
// offsets never carry into the swizzled bits, so inner addresses are
// base_reg + compile-time immediates (ptxas folds into LDSM/STS).
// ---------------------------------------------------------------------------
__global__ void __launch_bounds__(THREADS, 2)
arcface_gemm_kernel(const int* __restrict__ label,
                    float* __restrict__ cos_out, float* __restrict__ marg_out) {
    extern __shared__ char dsmem[];
    const uint32_t sbase = (smem_u32(dsmem) + 1023u) & ~1023u;

    const int tid  = threadIdx.x;
    const int lane = tid & 31;
    const int wid  = tid >> 5;
    const int warp_m = wid & 1;     // 0..1  (64-row slab)
    const int warp_n = wid >> 1;    // 0..3  (32-col slab)
    const int n0 = blockIdx.x * BN;
    const int m0 = blockIdx.y * BM;

    // ---- loader precompute (per thread, hoisted swizzle) ----
    const int c16 = tid & 7;          // 16B chunk within 128B row
    const int rq  = tid >> 3;         // base row 0..31 (i adds 32)
    const uint32_t dst_off =
        (uint32_t)(rq * 128 + ((c16 * 16) ^ ((rq & 7) << 4)));
    const __half* aSrc = g_f16 + (size_t)(m0 + rq) * D_DIM + c16 * 8;
    uint32_t bOff[4];
    uint32_t bSz[4];
    #pragma unroll
    for (int i = 0; i < 4; i++) {
        int n = n0 + rq + i * 32;
        bOff[i] = (uint32_t)(((n < C_DIM) ? n : 0) * D_DIM + c16 * 8);
        bSz[i]  = (n < C_DIM) ? 16u : 0u;
    }

    // ---- ldmatrix precompute: per-lane swizzled column offsets ----
    const uint32_t xorv = (uint32_t)((lane & 7) << 4);
    uint32_t col_swz[4];
    #pragma unroll
    for (int ks = 0; ks < 4; ks++)
        col_swz[ks] = ((uint32_t)((lane >> 4) * 16 + ks * 32)) ^ xorv;
    const uint32_t a_row = (uint32_t)((warp_m * 64 + (lane & 15)) * 128);
    const uint32_t b_row = (uint32_t)((warp_n * 32 + (lane & 15)) * 128);

    float acc[4][4][4];
    #pragma unroll
    for (int mt = 0; mt < 4; mt++)
        #pragma unroll
        for (int nt = 0; nt < 4; nt++)
            #pragma unroll
            for (int e = 0; e < 4; e++) acc[mt][nt][e] = 0.0f;

    // ---- prologue: fill stages 0,1 ----
    #pragma unroll
    for (int p = 0; p < STAGES - 1; p++) {
        const uint32_t sA = sbase + p * STAGE_BYTES;
        const uint32_t sB = sA + BM * 128;
        const int kk = p * BK;
        #pragma unroll
        for (int i = 0; i < 4; i++)
            cp_async16(sA + dst_off + i * 4096, aSrc + (size_t)i * 32 * D_DIM + kk, 16u);
        #pragma unroll
        for (int i = 0; i < 4; i++)
            cp_async16(sB + dst_off + i * 4096, g_w16 + bOff[i] + kk, bSz[i]);
        CP_COMMIT();
    }

    for (int k = 0; k < NK; k++) {
        CP_WAIT(1);
        __syncthreads();

        if (k + STAGES - 1 < NK) {
            const int st = (k + STAGES - 1) % STAGES;
            const uint32_t sA = sbase + st * STAGE_BYTES;
            const uint32_t sB = sA + BM * 128;
            const int kk = (k + STAGES - 1) * BK;
            #pragma unroll
            for (int i = 0; i < 4; i++)
                cp_async16(sA + dst_off + i * 4096, aSrc + (size_t)i * 32 * D_DIM + kk, 16u);
            #pragma unroll
            for (int i = 0; i < 4; i++)
                cp_async16(sB + dst_off + i * 4096, g_w16 + bOff[i] + kk, bSz[i]);
        }
        CP_COMMIT();

        const uint32_t sA = sbase + (k % STAGES) * STAGE_BYTES;
        const uint32_t sB = sA + BM * 128;
        const uint32_t aB = sA + a_row;
        const uint32_t bB = sB + b_row;

        #pragma unroll
        for (int ks = 0; ks < 4; ks++) {
            const uint32_t ab = aB + col_swz[ks];
            const uint32_t bb = bB + col_swz[ks];
            uint32_t a_frag[4][4];
            #pragma unroll
            for (int mt = 0; mt < 4; mt++)
                LDSM_X4(a_frag[mt], ab + mt * 2048);   // imm-foldable
            uint32_t b_frag[2][4];
            #pragma unroll
            for (int g = 0; g < 2; g++)
                LDSM_X4(b_frag[g], bb + g * 2048);     // imm-foldable
            #pragma unroll
            for (int mt = 0; mt < 4; mt++)
                #pragma unroll
                for (int nt = 0; nt < 4; nt++) {
                    int g = nt >> 1, w = nt & 1;
                    mma_16816(acc[mt][nt], a_frag[mt],
                              b_frag[g][w], b_frag[g][w + 2]);
                }
        }
    }

    // --- fused epilogue: cos + ArcFace marginal logits, streaming stores ---
    const int mrow  = m0 + warp_m * 64 + (lane >> 2);
    const int ncol0 = n0 + warp_n * 32 + (lane & 3) * 2;
    #pragma unroll
    for (int mt = 0; mt < 4; mt++) {
        const int m1 = mrow + mt * 16;
        const int m2 = m1 + 8;
        const int lab1 = label[m1];
        const int lab2 = label[m2];
        #pragma unroll
        for (int nt = 0; nt < 4; nt++) {
            int n = ncol0 + nt * 8;
            if (n >= C_DIM) continue;
            float c0 = acc[mt][nt][0], c1 = acc[mt][nt][1];
            float c2 = acc[mt][nt][2], c3 = acc[mt][nt][3];
            size_t o1 = (size_t)m1 * C_DIM + n;
            size_t o2 = (size_t)m2 * C_DIM + n;
            st_cs_f2(cos_out + o1, c0, c1);
            st_cs_f2(cos_out + o2, c2, c3);
            float g0 = (n     == lab1) ? af_margin(c0) : AF_SCALE * c0;
            float g1 = (n + 1 == lab1) ? af_margin(c1) : AF_SCALE * c1;
            float g2 = (n     == lab2) ? af_margin(c2) : AF_SCALE * c2;
            float g3 = (n + 1 == lab2) ? af_margin(c3) : AF_SCALE * c3;
            st_cs_f2(marg_out + o1, g0, g1);
            st_cs_f2(marg_out + o2, g2, g3);
        }
    }
}

// ---------------------------------------------------------------------------
// Launch
// ---------------------------------------------------------------------------
extern "C" void kernel_launch(void* const* d_in, const int* in_sizes, int n_in,
                              void* d_out, int out_size) {
    const float* feat  = (const float*)d_in[0];
    const int*   label = (const int*)d_in[1];
    const float* wts   = (const float*)d_in[2];
    float* cos_out  = (float*)d_out;
    float* marg_out = cos_out + (size_t)B_ROWS * C_DIM;

    norm_rows_kernel<<<B_ROWS + C_DIM, 128>>>(feat, wts);

    cudaFuncSetAttribute(arcface_gemm_kernel,
                         cudaFuncAttributeMaxDynamicSharedMemorySize,
                         SMEM_BYTES);

    dim3 grid((C_DIM + BN - 1) / BN, B_ROWS / BM);   // (157, 32)
    arcface_gemm_kernel<<<grid, THREADS, SMEM_BYTES>>>(label, cos_out, marg_out);
}

// round 7
// speedup vs baseline: 1.2613x; 1.0091x over previous
#include <cuda_runtime.h>
#include <cuda_fp16.h>
#include <cstdint>

// ---------------------------------------------------------------------------
// Problem constants
// ---------------------------------------------------------------------------
#define B_ROWS 4096
#define D_DIM  512
#define C_DIM  20000

#define BM 128
#define BN 128
#define BK 64                   // 64 fp16 = 128B rows (SW128 atom)
#define NK (D_DIM / BK)         // 8 k-iterations
#define STAGES 3
#define THREADS 256

#define STAGE_BYTES ((BM + BN) * BK * 2)   // 32768
#define SMEM_BYTES  (STAGES * STAGE_BYTES + 1024)

static __device__ __half g_f16[(size_t)B_ROWS * D_DIM];   // normalized feat, fp16
static __device__ __half g_w16[(size_t)C_DIM * D_DIM];    // normalized weights, fp16

// ArcFace constants
#define AF_SCALE  30.0f
#define AF_COSM   0.87758256189037271612f   // cos(0.5)
#define AF_SINM   0.47942553860420300027f   // sin(0.5)
#define AF_THRESH (-0.87758256189037271612f)
#define AF_EXTV   (-0.23971276930210150013f) // -0.5*sin(0.5)

// ---------------------------------------------------------------------------
// PTX helpers
// ---------------------------------------------------------------------------
__device__ __forceinline__ uint32_t smem_u32(const void* p) {
    uint32_t a;
    asm("{ .reg .u64 t; cvta.to.shared.u64 t, %1; cvt.u32.u64 %0, t; }"
        : "=r"(a) : "l"(p));
    return a;
}

// full 16B copy, compile-time-foldable address forms
__device__ __forceinline__ void cp16(uint32_t dst, const void* src) {
    asm volatile("cp.async.cg.shared.global [%0], [%1], 16;"
                 :: "r"(dst), "l"(src));
}
// zfill variant for the tail n-CTA
__device__ __forceinline__ void cp16z(uint32_t dst, const void* src,
                                      uint32_t ssize) {
    asm volatile("cp.async.cg.shared.global [%0], [%1], 16, %2;"
                 :: "r"(dst), "l"(src), "r"(ssize));
}
#define CP_COMMIT() asm volatile("cp.async.commit_group;" ::: "memory")
#define CP_WAIT(n)  asm volatile("cp.async.wait_group %0;" :: "n"(n) : "memory")

#define LDSM_X4(r, addr) \
    asm volatile("ldmatrix.sync.aligned.m8n8.x4.shared.b16 {%0,%1,%2,%3}, [%4];" \
        : "=r"((r)[0]), "=r"((r)[1]), "=r"((r)[2]), "=r"((r)[3]) : "r"(addr))

__device__ __forceinline__ void mma_16816(float* d, const uint32_t* a,
                                          uint32_t b0, uint32_t b1) {
    asm volatile(
        "mma.sync.aligned.m16n8k16.row.col.f32.f16.f16.f32 "
        "{%0,%1,%2,%3}, {%4,%5,%6,%7}, {%8,%9}, {%0,%1,%2,%3};"
        : "+f"(d[0]), "+f"(d[1]), "+f"(d[2]), "+f"(d[3])
        : "r"(a[0]), "r"(a[1]), "r"(a[2]), "r"(a[3]), "r"(b0), "r"(b1));
}

__device__ __forceinline__ void st_cs_f2(float* p, float x, float y) {
    asm volatile("st.global.cs.v2.f32 [%0], {%1, %2};"
                 :: "l"(p), "f"(x), "f"(y) : "memory");
}

// ---------------------------------------------------------------------------
// Kernel 1: row L2-normalize fp32 -> fp16, both tensors in one launch
// ---------------------------------------------------------------------------
__global__ void norm_rows_kernel(const float* __restrict__ feat,
                                 const float* __restrict__ wts) {
    int row = blockIdx.x;
    const float* src;
    __half* dst;
    if (row < B_ROWS) {
        src = feat + (size_t)row * D_DIM;
        dst = g_f16 + (size_t)row * D_DIM;
    } else {
        row -= B_ROWS;
        src = wts + (size_t)row * D_DIM;
        dst = g_w16 + (size_t)row * D_DIM;
    }
    const int tid = threadIdx.x;
    const float4 v = reinterpret_cast<const float4*>(src)[tid];
    float ss = v.x * v.x + v.y * v.y + v.z * v.z + v.w * v.w;
    #pragma unroll
    for (int o = 16; o; o >>= 1) ss += __shfl_xor_sync(0xFFFFFFFFu, ss, o);
    __shared__ float ws[4];
    if ((tid & 31) == 0) ws[tid >> 5] = ss;
    __syncthreads();
    const float inv = rsqrtf(ws[0] + ws[1] + ws[2] + ws[3]);
    __half2 h0 = __floats2half2_rn(v.x * inv, v.y * inv);
    __half2 h1 = __floats2half2_rn(v.z * inv, v.w * inv);
    uint2 pk;
    pk.x = *reinterpret_cast<uint32_t*>(&h0);
    pk.y = *reinterpret_cast<uint32_t*>(&h1);
    reinterpret_cast<uint2*>(dst)[tid] = pk;
}

// ---------------------------------------------------------------------------
// ArcFace margin for the label column
// ---------------------------------------------------------------------------
__device__ __forceinline__ float af_margin(float c) {
    if (c > AF_THRESH) {
        float s = sqrtf(fmaxf(0.0f, 1.0f - c * c));
        return AF_SCALE * (c * AF_COSM - s * AF_SINM);
    }
    return AF_SCALE * (c + AF_EXTV);
}

// ---------------------------------------------------------------------------
// GEMM tile body, templated on FULL (no n-bounds anywhere for 156/157 CTAs).
// k-loop fully unrolled: every smem stage offset, every global src offset,
// and every LDSM offset is a compile-time immediate off a handful of regs.
// ---------------------------------------------------------------------------
template <bool FULL>
__device__ __forceinline__ void gemm_tile(const int* __restrict__ label,
                                          float* __restrict__ cos_out,
                                          float* __restrict__ marg_out,
                                          uint32_t sbase, int m0, int n0) {
    const int tid  = threadIdx.x;
    const int lane = tid & 31;
    const int wid  = tid >> 5;
    const int warp_m = wid & 1;     // 0..1  (64-row slab)
    const int warp_n = wid >> 1;    // 0..3  (32-col slab)

    // ---- loader bases (per thread) ----
    const int c16 = tid & 7;          // 16B chunk within 128B row
    const int rq  = tid >> 3;         // base row 0..31 (i adds 32)
    const uint32_t dA = sbase + (uint32_t)(rq * 128 + ((c16 * 16) ^ ((rq & 7) << 4)));
    const uint32_t dB = dA + 16384;

    const __half* aSrc = g_f16 + (size_t)(m0 + rq) * D_DIM + c16 * 8;
    const __half* bSrc = nullptr;     // FULL path: single base, imm offsets
    const __half* bSrcT[4];
    uint32_t bSz[4];
    if constexpr (FULL) {
        bSrc = g_w16 + (size_t)(n0 + rq) * D_DIM + c16 * 8;
    } else {
        #pragma unroll
        for (int i = 0; i < 4; i++) {
            int n = n0 + rq + i * 32;
            bSrcT[i] = g_w16 + (size_t)((n < C_DIM) ? n : 0) * D_DIM + c16 * 8;
            bSz[i]   = (n < C_DIM) ? 16u : 0u;
        }
    }

    // ---- ldmatrix bases: 8 regs, everything else immediate ----
    const uint32_t xorv = (uint32_t)((lane & 7) << 4);
    const uint32_t a_row = sbase + (uint32_t)((warp_m * 64 + (lane & 15)) * 128);
    const uint32_t b_row = sbase + 16384u + (uint32_t)((warp_n * 32 + (lane & 15)) * 128);
    uint32_t aCol[4], bCol[4];
    #pragma unroll
    for (int ks = 0; ks < 4; ks++) {
        uint32_t c = ((uint32_t)((lane >> 4) * 16 + ks * 32)) ^ xorv;
        aCol[ks] = a_row + c;
        bCol[ks] = b_row + c;
    }

    float acc[4][4][4];
    #pragma unroll
    for (int mt = 0; mt < 4; mt++)
        #pragma unroll
        for (int nt = 0; nt < 4; nt++)
            #pragma unroll
            for (int e = 0; e < 4; e++) acc[mt][nt][e] = 0.0f;

    // stage loader: st and kk are compile-time constants at every call site
    auto load_stage = [&](int st, int kk) {
        #pragma unroll
        for (int i = 0; i < 4; i++)
            cp16(dA + st * STAGE_BYTES + i * 4096, aSrc + kk + i * 16384);
        #pragma unroll
        for (int i = 0; i < 4; i++) {
            if constexpr (FULL)
                cp16(dB + st * STAGE_BYTES + i * 4096, bSrc + kk + i * 16384);
            else
                cp16z(dB + st * STAGE_BYTES + i * 4096, bSrcT[i] + kk, bSz[i]);
        }
    };

    // prologue: stages 0,1
    load_stage(0, 0);  CP_COMMIT();
    load_stage(1, BK); CP_COMMIT();

    #pragma unroll
    for (int k = 0; k < NK; k++) {
        CP_WAIT(1);
        __syncthreads();

        if (k + 2 < NK) load_stage((k + 2) % STAGES, (k + 2) * BK);
        CP_COMMIT();   // empty group in drain iters keeps wait count uniform

        const int st = (k % STAGES) * STAGE_BYTES;   // compile-time immediate

        #pragma unroll
        for (int ks = 0; ks < 4; ks++) {
            uint32_t a_frag[4][4];
            #pragma unroll
            for (int mt = 0; mt < 4; mt++)
                LDSM_X4(a_frag[mt], aCol[ks] + st + mt * 2048);
            uint32_t b_frag[2][4];
            #pragma unroll
            for (int g = 0; g < 2; g++)
                LDSM_X4(b_frag[g], bCol[ks] + st + g * 2048);
            #pragma unroll
            for (int mt = 0; mt < 4; mt++)
                #pragma unroll
                for (int nt = 0; nt < 4; nt++) {
                    int g = nt >> 1, w = nt & 1;
                    mma_16816(acc[mt][nt], a_frag[mt],
                              b_frag[g][w], b_frag[g][w + 2]);
                }
        }
    }

    // --- fused epilogue: cos + ArcFace marginal logits, streaming stores ---
    const int mrow  = m0 + warp_m * 64 + (lane >> 2);
    const int ncol0 = n0 + warp_n * 32 + (lane & 3) * 2;
    #pragma unroll
    for (int mt = 0; mt < 4; mt++) {
        const int m1 = mrow + mt * 16;
        const int m2 = m1 + 8;
        const int lab1 = label[m1];
        const int lab2 = label[m2];
        #pragma unroll
        for (int nt = 0; nt < 4; nt++) {
            int n = ncol0 + nt * 8;
            if (!FULL && n >= C_DIM) continue;
            float c0 = acc[mt][nt][0], c1 = acc[mt][nt][1];
            float c2 = acc[mt][nt][2], c3 = acc[mt][nt][3];
            size_t o1 = (size_t)m1 * C_DIM + n;
            size_t o2 = (size_t)m2 * C_DIM + n;
            st_cs_f2(cos_out + o1, c0, c1);
            st_cs_f2(cos_out + o2, c2, c3);
            float g0 = (n     == lab1) ? af_margin(c0) : AF_SCALE * c0;
            float g1 = (n + 1 == lab1) ? af_margin(c1) : AF_SCALE * c1;
            float g2 = (n     == lab2) ? af_margin(c2) : AF_SCALE * c2;
            float g3 = (n + 1 == lab2) ? af_margin(c3) : AF_SCALE * c3;
            st_cs_f2(marg_out + o1, g0, g1);
            st_cs_f2(marg_out + o2, g2, g3);
        }
    }
}

__global__ void __launch_bounds__(THREADS, 2)
arcface_gemm_kernel(const int* __restrict__ label,
                    float* __restrict__ cos_out, float* __restrict__ marg_out) {
    extern __shared__ char dsmem[];
    const uint32_t sbase = (smem_u32(dsmem) + 1023u) & ~1023u;
    const int n0 = blockIdx.x * BN;
    const int m0 = blockIdx.y * BM;
    if (n0 + BN <= C_DIM)
        gemm_tile<true>(label, cos_out, marg_out, sbase, m0, n0);
    else
        gemm_tile<false>(label, cos_out, marg_out, sbase, m0, n0);
}

// ---------------------------------------------------------------------------
// Launch
// ---------------------------------------------------------------------------
extern "C" void kernel_launch(void* const* d_in, const int* in_sizes, int n_in,
                              void* d_out, int out_size) {
    const float* feat  = (const float*)d_in[0];
    const int*   label = (const int*)d_in[1];
    const float* wts   = (const float*)d_in[2];
    float* cos_out  = (float*)d_out;
    float* marg_out = cos_out + (size_t)B_ROWS * C_DIM;

    norm_rows_kernel<<<B_ROWS + C_DIM, 128>>>(feat, wts);

    cudaFuncSetAttribute(arcface_gemm_kernel,
                         cudaFuncAttributeMaxDynamicSharedMemorySize,
                         SMEM_BYTES);

    dim3 grid((C_DIM + BN - 1) / BN, B_ROWS / BM);   // (157, 32)
    arcface_gemm_kernel<<<grid, THREADS, SMEM_BYTES>>>(label, cos_out, marg_out);
}

// round 8
// speedup vs baseline: 1.2750x; 1.0109x over previous
#include <cuda_runtime.h>
#include <cuda_fp16.h>
#include <cstdint>

// ---------------------------------------------------------------------------
// Problem constants
// ---------------------------------------------------------------------------
#define B_ROWS 4096
#define D_DIM  512
#define C_DIM  20000

#define BM 128
#define BN 128
#define BK 64                   // 64 fp16 = 128B rows (SW128 atom)
#define NK (D_DIM / BK)         // 8 k-iterations
#define STAGES 3
#define THREADS 256

#define STAGE_BYTES ((BM + BN) * BK * 2)   // 32768
#define SMEM_BYTES  (STAGES * STAGE_BYTES + 1024)

static __device__ __half g_f16[(size_t)B_ROWS * D_DIM];   // normalized feat, fp16
static __device__ __half g_w16[(size_t)C_DIM * D_DIM];    // normalized weights, fp16

// ArcFace constants
#define AF_SCALE  30.0f
#define AF_COSM   0.87758256189037271612f   // cos(0.5)
#define AF_SINM   0.47942553860420300027f   // sin(0.5)
#define AF_THRESH (-0.87758256189037271612f)
#define AF_EXTV   (-0.23971276930210150013f) // -0.5*sin(0.5)

// ---------------------------------------------------------------------------
// PTX helpers
// ---------------------------------------------------------------------------
__device__ __forceinline__ uint32_t smem_u32(const void* p) {
    uint32_t a;
    asm("{ .reg .u64 t; cvta.to.shared.u64 t, %1; cvt.u32.u64 %0, t; }"
        : "=r"(a) : "l"(p));
    return a;
}

__device__ __forceinline__ void cp16(uint32_t dst, const void* src) {
    asm volatile("cp.async.cg.shared.global [%0], [%1], 16;"
                 :: "r"(dst), "l"(src));
}
__device__ __forceinline__ void cp16z(uint32_t dst, const void* src,
                                      uint32_t ssize) {
    asm volatile("cp.async.cg.shared.global [%0], [%1], 16, %2;"
                 :: "r"(dst), "l"(src), "r"(ssize));
}
#define CP_COMMIT() asm volatile("cp.async.commit_group;" ::: "memory")
#define CP_WAIT(n)  asm volatile("cp.async.wait_group %0;" :: "n"(n) : "memory")

#define LDSM_X4(r, addr) \
    asm volatile("ldmatrix.sync.aligned.m8n8.x4.shared.b16 {%0,%1,%2,%3}, [%4];" \
        : "=r"((r)[0]), "=r"((r)[1]), "=r"((r)[2]), "=r"((r)[3]) : "r"(addr))

__device__ __forceinline__ void mma_16816(float* d, const uint32_t* a,
                                          uint32_t b0, uint32_t b1) {
    asm volatile(
        "mma.sync.aligned.m16n8k16.row.col.f32.f16.f16.f32 "
        "{%0,%1,%2,%3}, {%4,%5,%6,%7}, {%8,%9}, {%0,%1,%2,%3};"
        : "+f"(d[0]), "+f"(d[1]), "+f"(d[2]), "+f"(d[3])
        : "r"(a[0]), "r"(a[1]), "r"(a[2]), "r"(a[3]), "r"(b0), "r"(b1));
}

__device__ __forceinline__ void st_cs_f2(float* p, float x, float y) {
    asm volatile("st.global.cs.v2.f32 [%0], {%1, %2};"
                 :: "l"(p), "f"(x), "f"(y) : "memory");
}

// ---------------------------------------------------------------------------
// Kernel 1: row L2-normalize fp32 -> fp16, both tensors in one launch
// ---------------------------------------------------------------------------
__global__ void norm_rows_kernel(const float* __restrict__ feat,
                                 const float* __restrict__ wts) {
    int row = blockIdx.x;
    const float* src;
    __half* dst;
    if (row < B_ROWS) {
        src = feat + (size_t)row * D_DIM;
        dst = g_f16 + (size_t)row * D_DIM;
    } else {
        row -= B_ROWS;
        src = wts + (size_t)row * D_DIM;
        dst = g_w16 + (size_t)row * D_DIM;
    }
    const int tid = threadIdx.x;
    const float4 v = reinterpret_cast<const float4*>(src)[tid];
    float ss = v.x * v.x + v.y * v.y + v.z * v.z + v.w * v.w;
    #pragma unroll
    for (int o = 16; o; o >>= 1) ss += __shfl_xor_sync(0xFFFFFFFFu, ss, o);
    __shared__ float ws[4];
    if ((tid & 31) == 0) ws[tid >> 5] = ss;
    __syncthreads();
    const float inv = rsqrtf(ws[0] + ws[1] + ws[2] + ws[3]);
    __half2 h0 = __floats2half2_rn(v.x * inv, v.y * inv);
    __half2 h1 = __floats2half2_rn(v.z * inv, v.w * inv);
    uint2 pk;
    pk.x = *reinterpret_cast<uint32_t*>(&h0);
    pk.y = *reinterpret_cast<uint32_t*>(&h1);
    reinterpret_cast<uint2*>(dst)[tid] = pk;
}

// ---------------------------------------------------------------------------
// ArcFace margin for the label column
// ---------------------------------------------------------------------------
__device__ __forceinline__ float af_margin(float c) {
    if (c > AF_THRESH) {
        float s = sqrtf(fmaxf(0.0f, 1.0f - c * c));
        return AF_SCALE * (c * AF_COSM - s * AF_SINM);
    }
    return AF_SCALE * (c + AF_EXTV);
}

// ---------------------------------------------------------------------------
// GEMM tile body. Fully unrolled k-loop; fragment double-buffering across ks
// hides LDSM latency behind the 16 MMAs of the previous ks-step.
// Swizzled column offset: col(ks) = col0 ^ (ks<<5), valid since
// (lane>>4)*16 is bit 4 and ks*32 is bits 5-6 (bit-disjoint).
// ---------------------------------------------------------------------------
template <bool FULL>
__device__ __forceinline__ void gemm_tile(const int* __restrict__ label,
                                          float* __restrict__ cos_out,
                                          float* __restrict__ marg_out,
                                          uint32_t sbase, int m0, int n0) {
    const int tid  = threadIdx.x;
    const int lane = tid & 31;
    const int wid  = tid >> 5;
    const int warp_m = wid & 1;     // 0..1  (64-row slab)
    const int warp_n = wid >> 1;    // 0..3  (32-col slab)

    // ---- loader bases (per thread) ----
    const int c16 = tid & 7;
    const int rq  = tid >> 3;
    const uint32_t dA = sbase + (uint32_t)(rq * 128 + ((c16 * 16) ^ ((rq & 7) << 4)));
    const uint32_t dB = dA + 16384;

    const __half* aSrc = g_f16 + (size_t)(m0 + rq) * D_DIM + c16 * 8;
    const __half* bSrc = nullptr;
    const __half* bSrcT[4];
    uint32_t bSz[4];
    if constexpr (FULL) {
        bSrc = g_w16 + (size_t)(n0 + rq) * D_DIM + c16 * 8;
    } else {
        #pragma unroll
        for (int i = 0; i < 4; i++) {
            int n = n0 + rq + i * 32;
            bSrcT[i] = g_w16 + (size_t)((n < C_DIM) ? n : 0) * D_DIM + c16 * 8;
            bSz[i]   = (n < C_DIM) ? 16u : 0u;
        }
    }

    // ---- ldmatrix bases (2 regs + XOR-derived per-ks column) ----
    const uint32_t col0 =
        ((uint32_t)((lane >> 4) * 16)) ^ ((uint32_t)((lane & 7) << 4));
    const uint32_t a_row = sbase + (uint32_t)((warp_m * 64 + (lane & 15)) * 128);
    const uint32_t b_row = sbase + 16384u + (uint32_t)((warp_n * 32 + (lane & 15)) * 128);

    float acc[4][4][4];
    #pragma unroll
    for (int mt = 0; mt < 4; mt++)
        #pragma unroll
        for (int nt = 0; nt < 4; nt++)
            #pragma unroll
            for (int e = 0; e < 4; e++) acc[mt][nt][e] = 0.0f;

    auto load_stage = [&](int st, int kk) {
        #pragma unroll
        for (int i = 0; i < 4; i++)
            cp16(dA + st * STAGE_BYTES + i * 4096, aSrc + kk + i * 16384);
        #pragma unroll
        for (int i = 0; i < 4; i++) {
            if constexpr (FULL)
                cp16(dB + st * STAGE_BYTES + i * 4096, bSrc + kk + i * 16384);
            else
                cp16z(dB + st * STAGE_BYTES + i * 4096, bSrcT[i] + kk, bSz[i]);
        }
    };

    // prologue: stages 0,1
    load_stage(0, 0);  CP_COMMIT();
    load_stage(1, BK); CP_COMMIT();

    // double-buffered fragment sets
    uint32_t afr[2][4][4];
    uint32_t bfr[2][2][4];

    #pragma unroll
    for (int k = 0; k < NK; k++) {
        CP_WAIT(1);
        __syncthreads();

        const int st = (k % STAGES) * STAGE_BYTES;   // compile-time under unroll
        const uint32_t aB = a_row + st;
        const uint32_t bB = b_row + st;

        // preload ks=0 fragments (critical path head)
        {
            const uint32_t c = col0;   // ks=0
            #pragma unroll
            for (int mt = 0; mt < 4; mt++)
                LDSM_X4(afr[0][mt], aB + c + mt * 2048);
            #pragma unroll
            for (int g = 0; g < 2; g++)
                LDSM_X4(bfr[0][g], bB + c + g * 2048);
        }

        // issue next-stage global prefetch while frags are in flight
        if (k + 2 < NK) load_stage((k + 2) % STAGES, (k + 2) * BK);
        CP_COMMIT();   // empty group in drain iters keeps wait count uniform

        #pragma unroll
        for (int ks = 0; ks < 4; ks++) {
            const int cur = ks & 1;
            if (ks < 3) {
                const int nxt = cur ^ 1;
                const uint32_t c = col0 ^ (uint32_t)((ks + 1) << 5);
                #pragma unroll
                for (int mt = 0; mt < 4; mt++)
                    LDSM_X4(afr[nxt][mt], aB + c + mt * 2048);
                #pragma unroll
                for (int g = 0; g < 2; g++)
                    LDSM_X4(bfr[nxt][g], bB + c + g * 2048);
            }
            #pragma unroll
            for (int mt = 0; mt < 4; mt++)
                #pragma unroll
                for (int nt = 0; nt < 4; nt++) {
                    int g = nt >> 1, w = nt & 1;
                    mma_16816(acc[mt][nt], afr[cur][mt],
                              bfr[cur][g][w], bfr[cur][g][w + 2]);
                }
        }
    }

    // --- fused epilogue: cos + ArcFace marginal logits, streaming stores ---
    const int mrow  = m0 + warp_m * 64 + (lane >> 2);
    const int ncol0 = n0 + warp_n * 32 + (lane & 3) * 2;
    #pragma unroll
    for (int mt = 0; mt < 4; mt++) {
        const int m1 = mrow + mt * 16;
        const int m2 = m1 + 8;
        const int lab1 = label[m1];
        const int lab2 = label[m2];
        #pragma unroll
        for (int nt = 0; nt < 4; nt++) {
            int n = ncol0 + nt * 8;
            if (!FULL && n >= C_DIM) continue;
            float c0 = acc[mt][nt][0], c1 = acc[mt][nt][1];
            float c2 = acc[mt][nt][2], c3 = acc[mt][nt][3];
            size_t o1 = (size_t)m1 * C_DIM + n;
            size_t o2 = (size_t)m2 * C_DIM + n;
            st_cs_f2(cos_out + o1, c0, c1);
            st_cs_f2(cos_out + o2, c2, c3);
            float g0 = (n     == lab1) ? af_margin(c0) : AF_SCALE * c0;
            float g1 = (n + 1 == lab1) ? af_margin(c1) : AF_SCALE * c1;
            float g2 = (n     == lab2) ? af_margin(c2) : AF_SCALE * c2;
            float g3 = (n + 1 == lab2) ? af_margin(c3) : AF_SCALE * c3;
            st_cs_f2(marg_out + o1, g0, g1);
            st_cs_f2(marg_out + o2, g2, g3);
        }
    }
}

__global__ void __launch_bounds__(THREADS, 2)
arcface_gemm_kernel(const int* __restrict__ label,
                    float* __restrict__ cos_out, float* __restrict__ marg_out) {
    extern __shared__ char dsmem[];
    const uint32_t sbase = (smem_u32(dsmem) + 1023u) & ~1023u;
    const int n0 = blockIdx.x * BN;
    const int m0 = blockIdx.y * BM;
    if (n0 + BN <= C_DIM)
        gemm_tile<true>(label, cos_out, marg_out, sbase, m0, n0);
    else
        gemm_tile<false>(label, cos_out, marg_out, sbase, m0, n0);
}

// ---------------------------------------------------------------------------
// Launch
// ---------------------------------------------------------------------------
extern "C" void kernel_launch(void* const* d_in, const int* in_sizes, int n_in,
                              void* d_out, int out_size) {
    const float* feat  = (const float*)d_in[0];
    const int*   label = (const int*)d_in[1];
    const float* wts   = (const float*)d_in[2];
    float* cos_out  = (float*)d_out;
    float* marg_out = cos_out + (size_t)B_ROWS * C_DIM;

    norm_rows_kernel<<<B_ROWS + C_DIM, 128>>>(feat, wts);

    cudaFuncSetAttribute(arcface_gemm_kernel,
                         cudaFuncAttributeMaxDynamicSharedMemorySize,
                         SMEM_BYTES);

    dim3 grid((C_DIM + BN - 1) / BN, B_ROWS / BM);   // (157, 32)
    arcface_gemm_kernel<<<grid, THREADS, SMEM_BYTES>>>(label, cos_out, marg_out);
}